// round 1
// baseline (speedup 1.0000x reference)
#include <cuda_runtime.h>

// Problem constants
#define BATCH 32768
#define NF 64
#define NB 33          // bounds per feature
#define NP 32          // pieces = NB-1
#define E  64          // embedding per feature

// Scratch: bias-folded prefix sums of W along the piece axis.
// C[f][j][e] = b[f][e] + sum_{i<j} W[f][i][e],  j in [0, 32]
__device__ float g_C[NF * NB * E];   // 64*33*64 floats = 528 KB

// ---------------------------------------------------------------------------
// Kernel 1: build prefix sums. 4096 threads, one per (f, e). Coalesced on e.
// ---------------------------------------------------------------------------
__global__ void pwl_prep(const float* __restrict__ W, const float* __restrict__ bias) {
    int idx = blockIdx.x * blockDim.x + threadIdx.x;
    if (idx >= NF * E) return;
    int f = idx >> 6;
    int e = idx & 63;
    float acc = bias[f * E + e];
    g_C[(f * NB + 0) * E + e] = acc;
#pragma unroll
    for (int i = 0; i < NP; i++) {
        acc += W[(f * NP + i) * E + e];
        g_C[(f * NB + (i + 1)) * E + e] = acc;
    }
}

// ---------------------------------------------------------------------------
// Kernel 2: one block per batch row. 512 threads.
//   Phase 1: threads 0..63 compute (j, frac) for their feature.
//   Phase 2: all 512 threads emit 1024 float4 stores (the 4096-float row).
// ---------------------------------------------------------------------------
__global__ __launch_bounds__(512, 4)
void pwl_main(const float* __restrict__ X,
              const float* __restrict__ bounds,
              const float* __restrict__ W,
              float* __restrict__ out) {
    __shared__ float s_frac[NF];
    __shared__ int   s_j[NF];

    int b = blockIdx.x;
    int t = threadIdx.x;

    if (t < NF) {
        float x = X[b * NF + t];
        const float* bd = bounds + t * NB;
        int j = 0;
#pragma unroll
        for (int k = 1; k <= NP; k++) j += (x >= bd[k]) ? 1 : 0;
        float frac = 0.0f;
        if (j < NP) {
            float lo = bd[j];
            float hi = bd[j + 1];
            frac = fminf(fmaxf((x - lo) / (hi - lo), 0.0f), 1.0f);
        }
        s_j[t]    = j;
        s_frac[t] = frac;
    }
    __syncthreads();

    float4* out4 = reinterpret_cast<float4*>(out + (size_t)b * (NF * E));

#pragma unroll
    for (int rep = 0; rep < 2; rep++) {
        int i  = t + rep * 512;          // 0..1023 float4 slots
        int f  = i >> 4;                 // 16 float4 per feature
        int e4 = i & 15;
        int   j    = s_j[f];
        float frac = s_frac[f];

        const float4 c = reinterpret_cast<const float4*>(g_C + ((f * NB + j) << 6))[e4];
        float4 r = c;
        if (j < NP) {
            const float4 w = reinterpret_cast<const float4*>(W + ((f * NP + j) << 6))[e4];
            r.x = fmaf(frac, w.x, c.x);
            r.y = fmaf(frac, w.y, c.y);
            r.z = fmaf(frac, w.z, c.z);
            r.w = fmaf(frac, w.w, c.w);
        }
        r.x = fmaxf(r.x, 0.0f);
        r.y = fmaxf(r.y, 0.0f);
        r.z = fmaxf(r.z, 0.0f);
        r.w = fmaxf(r.w, 0.0f);
        out4[i] = r;
    }
}

extern "C" void kernel_launch(void* const* d_in, const int* in_sizes, int n_in,
                              void* d_out, int out_size) {
    const float* X      = (const float*)d_in[0];   // (32768, 64)
    const float* bounds = (const float*)d_in[1];   // (64, 33)
    const float* W      = (const float*)d_in[2];   // (64, 32, 64)
    const float* bias   = (const float*)d_in[3];   // (64, 64)
    float* out = (float*)d_out;                    // (32768, 4096)

    pwl_prep<<<(NF * E + 255) / 256, 256>>>(W, bias);
    pwl_main<<<BATCH, 512>>>(X, bounds, W, out);
}

// round 2
// speedup vs baseline: 1.2097x; 1.2097x over previous
#include <cuda_runtime.h>
#include <cuda_fp16.h>

#define BATCH 32768
#define NF 64
#define NB 33          // bounds per feature
#define NP 32          // pieces = NB-1
#define E  64          // embedding per feature

// Packed table: P[f][j][e] = half2(c, w) where
//   c = b[f][e] + sum_{i<j} W[f][i][e]   (prefix at piece j)
//   w = W[f][j][e]                        (slope of piece j; 0 for j==32)
// Stored as float4 array for guaranteed 16B alignment (4 half2 per float4).
__device__ float4 g_P4[NF * NB * (E / 4)];      // 64*33*16 float4 = 540 KB

// Transposed bounds: bT[k][f] for coalesced per-feature search.
__device__ float g_bT[NB * NF];                  // 8.4 KB

// ---------------------------------------------------------------------------
// Prep: build packed fp16 (c,w) table + bounds transpose. One thread per (f,e).
// ---------------------------------------------------------------------------
__global__ void pwl_prep(const float* __restrict__ W,
                         const float* __restrict__ bias,
                         const float* __restrict__ bounds) {
    int idx = blockIdx.x * blockDim.x + threadIdx.x;
    if (idx < NB * NF) {
        // idx = k*64 + f  ->  bT[k][f] = bounds[f][k]
        int k = idx >> 6;
        int f = idx & 63;
        g_bT[idx] = bounds[f * NB + k];
    }
    if (idx >= NF * E) return;
    int f = idx >> 6;
    int e = idx & 63;
    __half2* P = reinterpret_cast<__half2*>(g_P4);
    float c = bias[f * E + e];
#pragma unroll
    for (int j = 0; j < NP; j++) {
        float w = W[(f * NP + j) * E + e];
        P[(f * NB + j) * E + e] = __floats2half2_rn(c, w);
        c += w;
    }
    P[(f * NB + NP) * E + e] = __floats2half2_rn(c, 0.0f);
}

// ---------------------------------------------------------------------------
// Main: one block per batch row, 512 threads.
//   Phase 1: threads 0..63 -> (table base index, frac) per feature.
//   Phase 2: 1024 float4 slots; each slot = 1 LDG.128 (4 c/w half2 pairs)
//            + 4 fma + 1 STG.128.
// ---------------------------------------------------------------------------
__global__ __launch_bounds__(512, 4)
void pwl_main(const float* __restrict__ X,
              float* __restrict__ out) {
    __shared__ float s_frac[NF];
    __shared__ int   s_base[NF];

    int b = blockIdx.x;
    int t = threadIdx.x;

    if (t < NF) {
        float x = X[b * NF + t];
        int j = 0;
#pragma unroll
        for (int k = 1; k <= NP; k++) j += (x >= g_bT[k * NF + t]) ? 1 : 0;
        float frac = 0.0f;
        if (j < NP) {
            float lo = g_bT[j * NF + t];
            float hi = g_bT[(j + 1) * NF + t];
            frac = fminf(fmaxf((x - lo) / (hi - lo), 0.0f), 1.0f);
        }
        s_base[t] = (t * NB + j) * (E / 4);   // float4 index of P[f][j][0]
        s_frac[t] = frac;
    }
    __syncthreads();

    float4* out4 = reinterpret_cast<float4*>(out + (size_t)b * (NF * E));

#pragma unroll
    for (int rep = 0; rep < 2; rep++) {
        int i  = t + rep * 512;              // 0..1023 float4 slots
        int f  = i >> 4;                     // 16 float4 per feature
        int e4 = i & 15;
        int   base = s_base[f];
        float frac = s_frac[f];

        float4 p = g_P4[base + e4];
        const __half2* h = reinterpret_cast<const __half2*>(&p);
        float4 r;
        float2 a0 = __half22float2(h[0]);
        float2 a1 = __half22float2(h[1]);
        float2 a2 = __half22float2(h[2]);
        float2 a3 = __half22float2(h[3]);
        r.x = fmaxf(fmaf(frac, a0.y, a0.x), 0.0f);
        r.y = fmaxf(fmaf(frac, a1.y, a1.x), 0.0f);
        r.z = fmaxf(fmaf(frac, a2.y, a2.x), 0.0f);
        r.w = fmaxf(fmaf(frac, a3.y, a3.x), 0.0f);
        out4[i] = r;
    }
}

extern "C" void kernel_launch(void* const* d_in, const int* in_sizes, int n_in,
                              void* d_out, int out_size) {
    const float* X      = (const float*)d_in[0];   // (32768, 64)
    const float* bounds = (const float*)d_in[1];   // (64, 33)
    const float* W      = (const float*)d_in[2];   // (64, 32, 64)
    const float* bias   = (const float*)d_in[3];   // (64, 64)
    float* out = (float*)d_out;                    // (32768, 4096)

    pwl_prep<<<(NF * E + 255) / 256, 256>>>(W, bias, bounds);
    pwl_main<<<BATCH, 512>>>(X, out);
}